// round 3
// baseline (speedup 1.0000x reference)
#include <cuda_runtime.h>
#include <math.h>

// ---------------------------------------------------------------------------
// BalancedFrequencyAttention, collapsed form.
//
// Derivation: gap = mean_{h,n} x_bal. Since sum_n D2[k,n] = 0 for k>=1 and
// = sqrt(240) for k=0 (DCT-II column sums), only the k=0 component of `bal`
// survives the mean. Tracing k=0 back through the low/high slicing of the
// W=480 DCT gives a per-element weight on x:
//   w(h,n) = c0 + [h>=80] * (0.4/48000) * g_{(h-80)%3}(n)
//   c0 = 0.6/sqrt(2)/48000
//   g_0(n) = cos((2n+1)pi/12) + cos((2n+1)pi/3)     (kk = 80, 320)
//   g_1(n) = cos((2n+1)pi/6)  + cos((2n+1)5pi/12)   (kk = 160, 400)
//   g_2(n) = cos((2n+1)pi/4)                        (kk = 240)
// All g_j are periodic in n with period 12.
// Then att = sigmoid(gap @ w1^T @ w2^T), out = x * att[:,:,None,None].
// ---------------------------------------------------------------------------

#define N_CH     1024      // B*C
#define Q_PER_CH 24000     // 200*480/4 float4 per channel
#define Q4_ROW   120       // 480/4 float4 per row

__device__ float d_gap[N_CH];
__device__ float d_att[N_CH];

// ---- Kernel 1: per-channel weighted reduction --------------------------------
__global__ __launch_bounds__(256) void reduce_kernel(const float* __restrict__ x) {
    __shared__ __align__(16) float tbl[4 * 480];
    __shared__ float wsum[8];

    const float c0  = 8.838834764831843e-06f;   // 0.6/sqrt(2)/48000
    const float inv = 8.333333333333334e-06f;   // 0.4/48000
    const float PI  = 3.14159265358979323846f;

    // Build the 4x480 weight table (only n%12 matters; args stay small so
    // cosf is ~1 ulp accurate).
    for (int n = threadIdx.x; n < 480; n += 256) {
        float a  = (float)(2 * (n % 12) + 1);
        float g0 = cosf(a * (PI / 12.f)) + cosf(a * (PI / 3.f));
        float g1 = cosf(a * (PI / 6.f))  + cosf(a * (5.f * PI / 12.f));
        float g2 = cosf(a * (PI / 4.f));
        tbl[n]          = c0;
        tbl[480  + n]   = c0 + inv * g0;
        tbl[960  + n]   = c0 + inv * g1;
        tbl[1440 + n]   = c0 + inv * g2;
    }
    __syncthreads();

    const float4* xc = reinterpret_cast<const float4*>(x) + (size_t)blockIdx.x * Q_PER_CH;
    float acc = 0.f;
    for (int q = threadIdx.x; q < Q_PER_CH; q += 256) {
        int h   = q / Q4_ROW;
        int n0  = (q - h * Q4_ROW) << 2;
        int cls = (h < 80) ? 0 : (1 + (h - 80) % 3);
        float4 v = xc[q];
        float4 w = *reinterpret_cast<const float4*>(tbl + cls * 480 + n0);
        acc += v.x * w.x + v.y * w.y + v.z * w.z + v.w * w.w;
    }

    #pragma unroll
    for (int o = 16; o; o >>= 1) acc += __shfl_xor_sync(0xffffffffu, acc, o);
    if ((threadIdx.x & 31) == 0) wsum[threadIdx.x >> 5] = acc;
    __syncthreads();
    if (threadIdx.x < 8) {
        float v = wsum[threadIdx.x];
        #pragma unroll
        for (int o = 4; o; o >>= 1) v += __shfl_xor_sync(0xffu, v, o);
        if (threadIdx.x == 0) d_gap[blockIdx.x] = v;
    }
}

// ---- Kernel 2: tiny MLP + sigmoid -------------------------------------------
__global__ __launch_bounds__(256) void mlp_kernel(const float* __restrict__ w1,
                                                  const float* __restrict__ w2) {
    __shared__ float sg[1024];
    __shared__ float sw1[32][129];   // padded: conflict-free column reads
    __shared__ float sw2[128][33];
    __shared__ float st1[256];
    int tid = threadIdx.x;

    for (int i = tid; i < 1024; i += 256) sg[i] = d_gap[i];
    for (int i = tid; i < 4096; i += 256) {
        sw1[i >> 7][i & 127] = w1[i];   // w1[j][c], j<32, c<128
        sw2[i >> 5][i & 31]  = w2[i];   // w2[c][j], c<128, j<32
    }
    __syncthreads();

    // Stage 1: t1[b][j] = sum_c gap[b][c] * w1[j][c]
    int b = tid >> 5, j = tid & 31;
    float s = 0.f;
    #pragma unroll 8
    for (int c = 0; c < 128; c++) s += sg[b * 128 + c] * sw1[j][c];
    st1[tid] = s;
    __syncthreads();

    // Stage 2: att[b][c] = sigmoid(sum_j t1[b][j] * w2[c][j])
    for (int i = tid; i < 1024; i += 256) {
        int bb = i >> 7, cc = i & 127;
        float z = 0.f;
        #pragma unroll
        for (int jj = 0; jj < 32; jj++) z += st1[bb * 32 + jj] * sw2[cc][jj];
        d_att[i] = 1.f / (1.f + expf(-z));
    }
}

// ---- Kernel 3: elementwise scale --------------------------------------------
__global__ __launch_bounds__(256) void scale_kernel(const float4* __restrict__ x,
                                                    float4* __restrict__ out) {
    int q  = blockIdx.x * 256 + threadIdx.x;
    int ch = blockIdx.y;
    if (q < Q_PER_CH) {
        float a = d_att[ch];
        size_t idx = (size_t)ch * Q_PER_CH + q;
        float4 v = x[idx];
        v.x *= a; v.y *= a; v.z *= a; v.w *= a;
        out[idx] = v;
    }
}

// ---- Launch ------------------------------------------------------------------
extern "C" void kernel_launch(void* const* d_in, const int* in_sizes, int n_in,
                              void* d_out, int out_size) {
    const float* x  = (const float*)d_in[0];
    const float* w1 = (const float*)d_in[1];
    const float* w2 = (const float*)d_in[2];
    float* out = (float*)d_out;

    reduce_kernel<<<N_CH, 256>>>(x);
    mlp_kernel<<<1, 256>>>(w1, w2);
    scale_kernel<<<dim3((Q_PER_CH + 255) / 256, N_CH), 256>>>(
        reinterpret_cast<const float4*>(x), reinterpret_cast<float4*>(out));
}

// round 4
// speedup vs baseline: 1.1041x; 1.1041x over previous
#include <cuda_runtime.h>
#include <math.h>

// ---------------------------------------------------------------------------
// BalancedFrequencyAttention, collapsed form (see R2 derivation):
//   gap[b,c] = sum_{h,n} x[b,c,h,n] * w(h,n)
//   w(h,n)   = c0 + [h>=80] * (0.4/48000) * g_{(h-80)%3}(n),  period-12 in n
//   att      = sigmoid(gap @ w1^T @ w2^T);  out = x * att[:,:,None,None]
// Pure HBM-bound: 1.18 GB total traffic.
// R3: 4-way channel-split reduction (kills wave tail), occupancy 6 blocks/SM,
//     streaming cache hints on the no-reuse tensors.
// ---------------------------------------------------------------------------

#define N_CH      1024      // B*C
#define Q_PER_CH  24000     // 200*480/4 float4 per channel
#define Q4_ROW    120       // 480/4 float4 per row
#define SPLIT     4         // blocks per channel in the reduction
#define Q_PER_BLK (Q_PER_CH / SPLIT)   // 6000 float4 = 50 rows
#define ROWS_BLK  50

__device__ float d_part[N_CH * SPLIT];
__device__ float d_att[N_CH];

// ---- Kernel 1: split per-channel weighted reduction --------------------------
__global__ __launch_bounds__(256, 6) void reduce_kernel(const float* __restrict__ x) {
    __shared__ __align__(16) float tbl[4 * 480];
    __shared__ float wsum[8];

    const float c0  = 8.838834764831843e-06f;   // 0.6/sqrt(2)/48000
    const float inv = 8.333333333333334e-06f;   // 0.4/48000
    const float PI  = 3.14159265358979323846f;

    for (int n = threadIdx.x; n < 480; n += 256) {
        float a  = (float)(2 * (n % 12) + 1);
        float g0 = cosf(a * (PI / 12.f)) + cosf(a * (PI / 3.f));
        float g1 = cosf(a * (PI / 6.f))  + cosf(a * (5.f * PI / 12.f));
        float g2 = cosf(a * (PI / 4.f));
        tbl[n]          = c0;
        tbl[480  + n]   = c0 + inv * g0;
        tbl[960  + n]   = c0 + inv * g1;
        tbl[1440 + n]   = c0 + inv * g2;
    }
    __syncthreads();

    const int ch   = blockIdx.x >> 2;
    const int sub  = blockIdx.x & 3;
    const int hb   = sub * ROWS_BLK;           // first row this block covers
    const float4* xc = reinterpret_cast<const float4*>(x)
                     + (size_t)ch * Q_PER_CH + sub * Q_PER_BLK;

    float acc0 = 0.f, acc1 = 0.f;
    #pragma unroll 4
    for (int q = threadIdx.x; q < Q_PER_BLK; q += 256) {
        int hl  = q / Q4_ROW;                  // 0..49
        int n0  = (q - hl * Q4_ROW) << 2;
        int h   = hb + hl;
        int cls = (h < 80) ? 0 : (1 + (h - 80) % 3);
        float4 v = __ldcs(&xc[q]);
        float4 w = *reinterpret_cast<const float4*>(tbl + cls * 480 + n0);
        acc0 += v.x * w.x + v.y * w.y;
        acc1 += v.z * w.z + v.w * w.w;
    }
    float acc = acc0 + acc1;

    #pragma unroll
    for (int o = 16; o; o >>= 1) acc += __shfl_xor_sync(0xffffffffu, acc, o);
    if ((threadIdx.x & 31) == 0) wsum[threadIdx.x >> 5] = acc;
    __syncthreads();
    if (threadIdx.x < 8) {
        float v = wsum[threadIdx.x];
        #pragma unroll
        for (int o = 4; o; o >>= 1) v += __shfl_xor_sync(0xffu, v, o);
        if (threadIdx.x == 0) d_part[blockIdx.x] = v;
    }
}

// ---- Kernel 2: fold partials + tiny MLP + sigmoid ----------------------------
__global__ __launch_bounds__(256) void mlp_kernel(const float* __restrict__ w1,
                                                  const float* __restrict__ w2) {
    __shared__ float sg[1024];
    __shared__ float sw1[32][129];   // padded: conflict-free column reads
    __shared__ float sw2[128][33];
    __shared__ float st1[256];
    int tid = threadIdx.x;

    for (int i = tid; i < 1024; i += 256) {
        const float4 p = *reinterpret_cast<const float4*>(&d_part[i * SPLIT]);
        sg[i] = (p.x + p.y) + (p.z + p.w);
    }
    for (int i = tid; i < 4096; i += 256) {
        sw1[i >> 7][i & 127] = w1[i];   // w1[j][c], j<32, c<128
        sw2[i >> 5][i & 31]  = w2[i];   // w2[c][j], c<128, j<32
    }
    __syncthreads();

    // Stage 1: t1[b][j] = sum_c gap[b][c] * w1[j][c]
    int b = tid >> 5, j = tid & 31;
    float s = 0.f;
    #pragma unroll 8
    for (int c = 0; c < 128; c++) s += sg[b * 128 + c] * sw1[j][c];
    st1[tid] = s;
    __syncthreads();

    // Stage 2: att[b][c] = sigmoid(sum_j t1[b][j] * w2[c][j])
    for (int i = tid; i < 1024; i += 256) {
        int bb = i >> 7, cc = i & 127;
        float z = 0.f;
        #pragma unroll
        for (int jj = 0; jj < 32; jj++) z += st1[bb * 32 + jj] * sw2[cc][jj];
        d_att[i] = 1.f / (1.f + expf(-z));
    }
}

// ---- Kernel 3: elementwise scale (streaming) ---------------------------------
__global__ __launch_bounds__(256) void scale_kernel(const float4* __restrict__ x,
                                                    float4* __restrict__ out) {
    int q  = blockIdx.x * 256 + threadIdx.x;
    int ch = blockIdx.y;
    if (q < Q_PER_CH) {
        float a = d_att[ch];
        size_t idx = (size_t)ch * Q_PER_CH + q;
        float4 v = __ldcs(&x[idx]);
        v.x *= a; v.y *= a; v.z *= a; v.w *= a;
        __stcs(&out[idx], v);
    }
}

// ---- Launch ------------------------------------------------------------------
extern "C" void kernel_launch(void* const* d_in, const int* in_sizes, int n_in,
                              void* d_out, int out_size) {
    const float* x  = (const float*)d_in[0];
    const float* w1 = (const float*)d_in[1];
    const float* w2 = (const float*)d_in[2];
    float* out = (float*)d_out;

    reduce_kernel<<<N_CH * SPLIT, 256>>>(x);
    mlp_kernel<<<1, 256>>>(w1, w2);
    scale_kernel<<<dim3((Q_PER_CH + 255) / 256, N_CH), 256>>>(
        reinterpret_cast<const float4*>(x), reinterpret_cast<float4*>(out));
}

// round 5
// speedup vs baseline: 1.1116x; 1.0068x over previous
#include <cuda_runtime.h>
#include <math.h>

// ---------------------------------------------------------------------------
// BalancedFrequencyAttention, collapsed form (see R2 derivation):
//   gap[b,c] = sum_{h,n} x[b,c,h,n] * w(h,n)
//   w(h,n)   = c0 + [h>=80] * (0.4/48000) * g_{(h-80)%3}(n),  period-12 in n
//   att      = sigmoid(gap @ w1^T @ w2^T);  out = x * att[:,:,None,None]
//
// R4: reduce re-partitioned so the weight is a per-thread REGISTER constant:
//   per channel -> 5 blocks: s=0,1 low (rows 40s..40s+39, weight=c0),
//   s=2,3,4 high class k=s-2 (rows 80+k+3m, m=0..39; (h-80)%3 == k fixed).
//   Inner loop = LDG.128 + 4 FFMA + ptr bump. smem ~0 -> 8 blocks/SM.
// ---------------------------------------------------------------------------

#define N_CH        1024      // B*C
#define Q_PER_CH    24000     // 200*480/4 float4 per channel
#define BLKS_PER_CH 5

__device__ float d_part[N_CH * BLKS_PER_CH];
__device__ float d_att[N_CH];

// ---- Kernel 1: weighted reduction, constant-register weights -----------------
__global__ __launch_bounds__(256, 8) void reduce_kernel(const float4* __restrict__ x) {
    const float c0  = 8.838834764831843e-06f;   // 0.6/sqrt(2)/48000
    const float inv = 8.333333333333334e-06f;   // 0.4/48000
    const float PI  = 3.14159265358979323846f;

    const int blk = blockIdx.x;
    const int ch  = blk / BLKS_PER_CH;
    const int s   = blk - ch * BLKS_PER_CH;

    const int t    = threadIdx.x;
    const int c4   = t & 127;          // float4 column (0..119 active)
    const int r    = t >> 7;           // row-within-pair (0/1)
    const bool act = (c4 < 120);

    // Per-thread constant weight (computed once).
    float4 w = make_float4(c0, c0, c0, c0);
    if (s >= 2) {
        const int k  = s - 2;
        const int n0 = c4 << 2;
        float g[4];
        #pragma unroll
        for (int e = 0; e < 4; e++) {
            float a = (float)(2 * ((n0 + e) % 12) + 1);
            float gv;
            if (k == 0)      gv = cosf(a * (PI / 12.f)) + cosf(a * (PI / 3.f));
            else if (k == 1) gv = cosf(a * (PI / 6.f))  + cosf(a * (5.f * PI / 12.f));
            else             gv = cosf(a * (PI / 4.f));
            g[e] = c0 + inv * gv;
        }
        w = make_float4(g[0], g[1], g[2], g[3]);
    }

    // Base offset + per-iteration stride (2 rows per iteration, 20 iterations).
    size_t base; int stride;
    if (s < 2) {                           // low: contiguous rows 40s .. 40s+39
        base   = (size_t)ch * Q_PER_CH + (size_t)(40 * s + r) * 120 + c4;
        stride = 240;                      // 2 rows
    } else {                               // high class k: rows 80+k+3m
        base   = (size_t)ch * Q_PER_CH + (size_t)(80 + (s - 2) + 3 * r) * 120 + c4;
        stride = 720;                      // 2 strided rows (6 physical rows)
    }

    float acc0 = 0.f, acc1 = 0.f;
    if (act) {
        const float4* p = x + base;
        #pragma unroll 5
        for (int i = 0; i < 20; i++) {
            float4 v = __ldcs(p);
            p += stride;
            acc0 += v.x * w.x + v.y * w.y;
            acc1 += v.z * w.z + v.w * w.w;
        }
    }
    float acc = acc0 + acc1;

    __shared__ float wsum[8];
    #pragma unroll
    for (int o = 16; o; o >>= 1) acc += __shfl_xor_sync(0xffffffffu, acc, o);
    if ((t & 31) == 0) wsum[t >> 5] = acc;
    __syncthreads();
    if (t < 8) {
        float v = wsum[t];
        #pragma unroll
        for (int o = 4; o; o >>= 1) v += __shfl_xor_sync(0xffu, v, o);
        if (t == 0) d_part[blk] = v;
    }
}

// ---- Kernel 2: fold partials + tiny MLP + sigmoid ----------------------------
__global__ __launch_bounds__(256) void mlp_kernel(const float* __restrict__ w1,
                                                  const float* __restrict__ w2) {
    __shared__ float sg[1024];
    __shared__ float sw1[32][129];   // padded: conflict-free column reads
    __shared__ float sw2[128][33];
    __shared__ float st1[256];
    int tid = threadIdx.x;

    for (int i = tid; i < 1024; i += 256) {
        const float* p = &d_part[i * BLKS_PER_CH];
        sg[i] = ((p[0] + p[1]) + (p[2] + p[3])) + p[4];
    }
    for (int i = tid; i < 4096; i += 256) {
        sw1[i >> 7][i & 127] = w1[i];   // w1[j][c], j<32, c<128
        sw2[i >> 5][i & 31]  = w2[i];   // w2[c][j], c<128, j<32
    }
    __syncthreads();

    // Stage 1: t1[b][j] = sum_c gap[b][c] * w1[j][c]
    int b = tid >> 5, j = tid & 31;
    float sacc = 0.f;
    #pragma unroll 8
    for (int c = 0; c < 128; c++) sacc += sg[b * 128 + c] * sw1[j][c];
    st1[tid] = sacc;
    __syncthreads();

    // Stage 2: att[b][c] = sigmoid(sum_j t1[b][j] * w2[c][j])
    for (int i = tid; i < 1024; i += 256) {
        int bb = i >> 7, cc = i & 127;
        float z = 0.f;
        #pragma unroll
        for (int jj = 0; jj < 32; jj++) z += st1[bb * 32 + jj] * sw2[cc][jj];
        d_att[i] = 1.f / (1.f + expf(-z));
    }
}

// ---- Kernel 3: elementwise scale, 2 float4 per thread ------------------------
__global__ __launch_bounds__(256) void scale_kernel(const float4* __restrict__ x,
                                                    float4* __restrict__ out) {
    const int ch = blockIdx.y;
    const float a = d_att[ch];
    const size_t base = (size_t)ch * Q_PER_CH;
    int q0 = blockIdx.x * 512 + threadIdx.x;
    int q1 = q0 + 256;

    float4 v0, v1;
    bool p0 = q0 < Q_PER_CH, p1 = q1 < Q_PER_CH;
    if (p0) v0 = __ldcs(&x[base + q0]);
    if (p1) v1 = __ldcs(&x[base + q1]);
    if (p0) { v0.x *= a; v0.y *= a; v0.z *= a; v0.w *= a; __stcs(&out[base + q0], v0); }
    if (p1) { v1.x *= a; v1.y *= a; v1.z *= a; v1.w *= a; __stcs(&out[base + q1], v1); }
}

// ---- Launch ------------------------------------------------------------------
extern "C" void kernel_launch(void* const* d_in, const int* in_sizes, int n_in,
                              void* d_out, int out_size) {
    const float* x  = (const float*)d_in[0];
    const float* w1 = (const float*)d_in[1];
    const float* w2 = (const float*)d_in[2];
    float* out = (float*)d_out;

    reduce_kernel<<<N_CH * BLKS_PER_CH, 256>>>(reinterpret_cast<const float4*>(x));
    mlp_kernel<<<1, 256>>>(w1, w2);
    scale_kernel<<<dim3((Q_PER_CH + 511) / 512, N_CH), 256>>>(
        reinterpret_cast<const float4*>(x), reinterpret_cast<float4*>(out));
}